// round 1
// baseline (speedup 1.0000x reference)
#include <cuda_runtime.h>
#include <math.h>

#define NPTS  32768      // 32*32*32 spatial points
#define CIN   64         // input channels (Cf = Cm)
#define NHD   16         // heads
#define HD    64         // head dim
#define CQ    1024       // NHD*HD
#define LNEPS 1e-5f

// ---------------- scratch (static device allocations; no cudaMalloc) ----------------
__device__ float g_xf[NPTS * CIN];     // LN(F), layout [p][c]
__device__ float g_xm[NPTS * CIN];     // LN(M), layout [p][c]
__device__ float g_qm[NPTS * CQ];      // qm, layout float4-chunked: [(h*16+c4)][p][4]
__device__ float g_G [CIN * CQ];       // G[i][h*64+j] = sum_d wf[i][h*64+d]*wm[j][h*64+d]
__device__ float g_u [CQ];             // u[h*64+j]    = sum_d wm[j][h*64+d]*bf[h*64+d]

// ---------------- kernel 0: per-head fused weight matrices ----------------
__global__ __launch_bounds__(256) void precompute_kernel(
    const float* __restrict__ wf, const float* __restrict__ wm,
    const float* __restrict__ bf)
{
    int h = blockIdx.x;                 // 16 blocks, one per head
    __shared__ float wfs[64][65];       // wfs[i][d]
    __shared__ float wms[64][65];       // wms[j][d]
    int tid = threadIdx.x;
    for (int idx = tid; idx < 4096; idx += 256) {
        int r = idx >> 6, d = idx & 63;
        wfs[r][d] = wf[r * CQ + h * 64 + d];
        wms[r][d] = wm[r * CQ + h * 64 + d];
    }
    __syncthreads();
    for (int idx = tid; idx < 4096; idx += 256) {
        int i = idx >> 6, j = idx & 63;
        float s = 0.f;
        #pragma unroll
        for (int d = 0; d < 64; d++) s += wfs[i][d] * wms[j][d];
        g_G[i * CQ + h * 64 + j] = s;
    }
    if (tid < 64) {
        float s = 0.f;
        #pragma unroll
        for (int d = 0; d < 64; d++) s += wms[tid][d] * bf[h * 64 + d];
        g_u[h * 64 + tid] = s;
    }
}

// ---------------- kernel 1: LayerNorm (channels-first -> [p][c]) ----------------
__global__ __launch_bounds__(128) void ln_kernel(
    const float* __restrict__ src,      // [64][32768]
    const float* __restrict__ gamma, const float* __restrict__ beta,
    int which)                          // 0 -> g_xf, 1 -> g_xm
{
    __shared__ float gs[64], bs[64];
    int tid = threadIdx.x;
    if (tid < 64) { gs[tid] = gamma[tid]; bs[tid] = beta[tid]; }
    __syncthreads();

    int p = blockIdx.x * 128 + tid;
    float v[64];
    float mean = 0.f;
    #pragma unroll
    for (int c = 0; c < 64; c++) { v[c] = src[c * NPTS + p]; mean += v[c]; }
    mean *= (1.f / 64.f);
    float var = 0.f;
    #pragma unroll
    for (int c = 0; c < 64; c++) { float d = v[c] - mean; var += d * d; }
    float rstd = rsqrtf(var * (1.f / 64.f) + LNEPS);

    float* dst = which ? g_xm : g_xf;
    #pragma unroll
    for (int c = 0; c < 64; c += 4) {
        float4 o;
        o.x = (v[c + 0] - mean) * rstd * gs[c + 0] + bs[c + 0];
        o.y = (v[c + 1] - mean) * rstd * gs[c + 1] + bs[c + 1];
        o.z = (v[c + 2] - mean) * rstd * gs[c + 2] + bs[c + 2];
        o.w = (v[c + 3] - mean) * rstd * gs[c + 3] + bs[c + 3];
        *(float4*)&dst[p * 64 + c] = o;
    }
}

// ---------------- kernel 2: qm GEMM  [32768,64] x [64,1024] ----------------
// BM=128, BN=64, K=64 (single slab). 256 threads, 8x4 register tile.
__global__ __launch_bounds__(256) void qm_gemm_kernel()
{
    __shared__ float As[64][128];   // As[k][m]
    __shared__ float Bs[64][64];    // Bs[k][n]
    int tid = threadIdx.x;
    int n0 = blockIdx.x * 64;
    int p0 = blockIdx.y * 128;

    // load A tile (transpose [p][c] -> [c][m])
    {
        int r  = tid & 127;
        int cb = (tid >> 7) * 32;
        #pragma unroll
        for (int i = 0; i < 8; i++) {
            float4 a = *(const float4*)&g_xf[(p0 + r) * 64 + cb + i * 4];
            As[cb + i * 4 + 0][r] = a.x;
            As[cb + i * 4 + 1][r] = a.y;
            As[cb + i * 4 + 2][r] = a.z;
            As[cb + i * 4 + 3][r] = a.w;
        }
    }
    // load B tile
    #pragma unroll
    for (int f = 0; f < 4; f++) {
        int idx = tid + f * 256;            // float4 index within 64x64 tile
        int c = idx >> 4, n = (idx & 15) * 4;
        *(float4*)&Bs[c][n] = *(const float4*)&g_G[c * CQ + n0 + n];
    }
    __syncthreads();

    int tx = tid & 15;        // n
    int ty = tid >> 4;        // m
    float acc[8][4];
    #pragma unroll
    for (int i = 0; i < 8; i++)
        #pragma unroll
        for (int j = 0; j < 4; j++) acc[i][j] = 0.f;

    #pragma unroll
    for (int k = 0; k < 64; k++) {
        float4 a0 = *(float4*)&As[k][ty * 8];
        float4 a1 = *(float4*)&As[k][ty * 8 + 4];
        float4 b  = *(float4*)&Bs[k][tx * 4];
        float av[8] = {a0.x, a0.y, a0.z, a0.w, a1.x, a1.y, a1.z, a1.w};
        float bv[4] = {b.x, b.y, b.z, b.w};
        #pragma unroll
        for (int i = 0; i < 8; i++)
            #pragma unroll
            for (int j = 0; j < 4; j++)
                acc[i][j] += av[i] * bv[j];
    }

    // epilogue: += u, write to chunked layout [(h*16+c4)][p]
    int n  = n0 + tx * 4;
    int hq = n >> 6;
    int c4 = (n & 63) >> 2;
    float4 uu = *(const float4*)&g_u[n];
    float4* outp = (float4*)g_qm;
    long plane = (long)(hq * 16 + c4) * NPTS;
    #pragma unroll
    for (int i = 0; i < 8; i++) {
        int p = p0 + ty * 8 + i;
        float4 o = make_float4(acc[i][0] + uu.x, acc[i][1] + uu.y,
                               acc[i][2] + uu.z, acc[i][3] + uu.w);
        outp[plane + p] = o;
    }
}

// ---------------- kernel 3: neighborhood attention ----------------
// Tile: 2(z) x 2(y) x 32(t) = 128 points. Halo 4x4x34 * 64ch fp32 in smem (136 KB).
// 256 threads: tid>>7 selects head-half (0..7 / 8..15); per head-group of 4,
// each halo float4 load feeds 16 FMAs (4 heads x 4 ch).
__global__ __launch_bounds__(256) void attn_kernel(
    const float* __restrict__ rpb, float* __restrict__ out)
{
    extern __shared__ float4 halo[];    // [c4=16][hz=4][hy=4][ht=34]
    __shared__ float rpb_s[NHD * 27];

    int tid = threadIdx.x;
    int z0 = (blockIdx.x >> 4) * 2;
    int y0 = (blockIdx.x & 15) * 2;

    for (int i = tid; i < NHD * 27; i += 256) rpb_s[i] = rpb[i];

    const float4* xm4 = (const float4*)g_xm;
    #pragma unroll 1
    for (int c4 = 0; c4 < 16; c4++) {
        for (int ptI = tid; ptI < 544; ptI += 256) {
            int hz = ptI / 136;
            int r  = ptI - hz * 136;
            int hy = r / 34;
            int ht = r - hy * 34;
            int gz = z0 - 1 + hz, gy = y0 - 1 + hy, gt = ht - 1;
            float4 v = make_float4(0.f, 0.f, 0.f, 0.f);
            if ((unsigned)gz < 32u && (unsigned)gy < 32u && (unsigned)gt < 32u)
                v = xm4[(gz * 1024 + gy * 32 + gt) * 16 + c4];
            halo[((c4 * 4 + hz) * 4 + hy) * 34 + ht] = v;
        }
    }
    __syncthreads();

    int half = tid >> 7;
    int ptid = tid & 127;
    int pz = ptid >> 6, py = (ptid >> 5) & 1, pt = ptid & 31;
    int gp = (z0 + pz) * 1024 + (y0 + py) * 32 + pt;
    const float4* qm4 = (const float4*)g_qm;

    #pragma unroll 1
    for (int hg = 0; hg < 2; hg++) {
        int h0 = half * 8 + hg * 4;

        float sc[4][27];
        #pragma unroll
        for (int hh = 0; hh < 4; hh++)
            #pragma unroll
            for (int o = 0; o < 27; o++)
                sc[hh][o] = rpb_s[(h0 + hh) * 27 + o];

        // prefetch qm for c4 = 0
        float4 qv[4], qvn[4];
        #pragma unroll
        for (int hh = 0; hh < 4; hh++)
            qv[hh] = qm4[((h0 + hh) * 16 + 0) * NPTS + gp];

        #pragma unroll 1
        for (int c4 = 0; c4 < 16; c4++) {
            if (c4 < 15) {
                #pragma unroll
                for (int hh = 0; hh < 4; hh++)
                    qvn[hh] = qm4[((h0 + hh) * 16 + (c4 + 1)) * NPTS + gp];
            }
            #pragma unroll
            for (int dz = 0; dz < 3; dz++)
                #pragma unroll
                for (int dy = 0; dy < 3; dy++)
                    #pragma unroll
                    for (int dx = 0; dx < 3; dx++) {
                        float4 kv = halo[((c4 * 4 + pz + dz) * 4 + (py + dy)) * 34 + (pt + dx)];
                        int off = (dz * 3 + dy) * 3 + dx;
                        #pragma unroll
                        for (int hh = 0; hh < 4; hh++) {
                            sc[hh][off] += qv[hh].x * kv.x;
                            sc[hh][off] += qv[hh].y * kv.y;
                            sc[hh][off] += qv[hh].z * kv.z;
                            sc[hh][off] += qv[hh].w * kv.w;
                        }
                    }
            #pragma unroll
            for (int hh = 0; hh < 4; hh++) qv[hh] = qvn[hh];
        }

        // softmax over 27 + value-grid projection (V[k] = (dz-1, dy-1, dx-1))
        #pragma unroll
        for (int hh = 0; hh < 4; hh++) {
            int h = h0 + hh;
            float m = sc[hh][0];
            #pragma unroll
            for (int o = 1; o < 27; o++) m = fmaxf(m, sc[hh][o]);
            float sum = 0.f, xz = 0.f, xy = 0.f, xt = 0.f;
            #pragma unroll
            for (int dz = 0; dz < 3; dz++)
                #pragma unroll
                for (int dy = 0; dy < 3; dy++)
                    #pragma unroll
                    for (int dx = 0; dx < 3; dx++) {
                        int o = (dz * 3 + dy) * 3 + dx;
                        float e = __expf(sc[hh][o] - m);
                        sum += e;
                        xz += e * (float)(dz - 1);
                        xy += e * (float)(dy - 1);
                        xt += e * (float)(dx - 1);
                    }
            float inv = 1.f / sum;
            out[(h * 3 + 0) * NPTS + gp] = xz * inv;
            out[(h * 3 + 1) * NPTS + gp] = xy * inv;
            out[(h * 3 + 2) * NPTS + gp] = xt * inv;
        }
    }
}

// ---------------- launch ----------------
extern "C" void kernel_launch(void* const* d_in, const int* in_sizes, int n_in,
                              void* d_out, int out_size)
{
    const float* F       = (const float*)d_in[0];
    const float* M       = (const float*)d_in[1];
    const float* gamma_f = (const float*)d_in[2];
    const float* beta_f  = (const float*)d_in[3];
    const float* w_f     = (const float*)d_in[4];
    const float* b_f     = (const float*)d_in[5];
    const float* gamma_m = (const float*)d_in[6];
    const float* beta_m  = (const float*)d_in[7];
    const float* w_m     = (const float*)d_in[8];
    /* b_m (d_in[9]) is softmax-invariant and provably drops out */
    const float* rpb     = (const float*)d_in[10];
    float* out = (float*)d_out;

    precompute_kernel<<<16, 256>>>(w_f, w_m, b_f);

    ln_kernel<<<NPTS / 128, 128>>>(F, gamma_f, beta_f, 0);
    ln_kernel<<<NPTS / 128, 128>>>(M, gamma_m, beta_m, 1);

    qm_gemm_kernel<<<dim3(CQ / 64, NPTS / 128), 256>>>();

    const int haloBytes = 16 * 4 * 4 * 34 * (int)sizeof(float4);   // 139264
    cudaFuncSetAttribute(attn_kernel, cudaFuncAttributeMaxDynamicSharedMemorySize, haloBytes);
    attn_kernel<<<256, 256, haloBytes>>>(rpb, out);
}